// round 11
// baseline (speedup 1.0000x reference)
#include <cuda_runtime.h>
#include <cstdint>
#include <math.h>

// One kernel. Cluster = 2 CTAs = one batch b. Each CTA: 1024 rows of
// energies[b] computed into smem (dot loop identical to the 80.4us R7 one),
// then cluster-wide softmax via DSMEM mailbox + barrier.cluster (HW barrier;
// NO gpu-scope atomics -- those cost ~2x in R3/R4/R8).
#define THREADS 1024

__global__ void __launch_bounds__(THREADS, 1) __cluster_dims__(2, 1, 1)
attn_cluster_kernel(const float* __restrict__ hidden,   // [64, 1024]
                    const float* __restrict__ enc,      // [2048, 64, 1024]
                    float* __restrict__ out)            // [64, 2048]
{
    __shared__ float4 sh_h[256];     // hidden[b], 4KB
    __shared__ float  sh_e[1024];    // this CTA's half of the energies
    __shared__ float  red[36];       // [0..31] warp partials, [32] my max,
                                     // [33] peer max, [34] my sum, [35] peer sum

    int tid  = threadIdx.x;
    int warp = tid >> 5;
    int lane = tid & 31;

    unsigned int rank;
    asm("mov.u32 %0, %%cluster_ctarank;" : "=r"(rank));
    int b = blockIdx.x >> 1;

    if (tid < 256)
        sh_h[tid] = reinterpret_cast<const float4*>(hidden + (size_t)b * 1024)[tid];
    __syncthreads();

    // ---- dot: each warp computes 32 consecutive rows ----
    int s0 = (int)rank * 1024 + warp * 32;
    for (int r = 0; r < 32; r++) {
        const float4* row = reinterpret_cast<const float4*>(
            enc + ((size_t)(s0 + r) * 64 + b) * 1024);
        float acc = 0.0f;
#pragma unroll
        for (int i = 0; i < 8; i++) {
            float4 e  = __ldcs(&row[lane + i * 32]);
            float4 hv = sh_h[lane + i * 32];
            acc = fmaf(e.x, hv.x, acc);
            acc = fmaf(e.y, hv.y, acc);
            acc = fmaf(e.z, hv.z, acc);
            acc = fmaf(e.w, hv.w, acc);
        }
#pragma unroll
        for (int o = 16; o; o >>= 1)
            acc += __shfl_xor_sync(0xffffffffu, acc, o);
        if (lane == 0)
            sh_e[warp * 32 + r] = acc;
    }
    __syncthreads();

    // ---- local max (1024 values, 1/thread) ----
    float m = sh_e[tid];
#pragma unroll
    for (int o = 16; o; o >>= 1)
        m = fmaxf(m, __shfl_xor_sync(0xffffffffu, m, o));
    if (lane == 0) red[warp] = m;
    __syncthreads();
    if (warp == 0) {
        float x = red[lane];
#pragma unroll
        for (int o = 16; o; o >>= 1)
            x = fmaxf(x, __shfl_xor_sync(0xffffffffu, x, o));
        if (lane == 0) {
            red[32] = x;
            // push my max into peer CTA's red[33]
            unsigned int la = (unsigned int)__cvta_generic_to_shared(&red[33]);
            unsigned int pa;
            asm("mapa.shared::cluster.u32 %0, %1, %2;"
                : "=r"(pa) : "r"(la), "r"(rank ^ 1u));
            asm volatile("st.shared::cluster.f32 [%0], %1;"
                         :: "r"(pa), "f"(x) : "memory");
        }
    }
    asm volatile("barrier.cluster.arrive.aligned;" ::: "memory");
    asm volatile("barrier.cluster.wait.aligned;"   ::: "memory");
    float gm = fmaxf(red[32], red[33]);

    // ---- exp + local sum ----
    float e = __expf(sh_e[tid] - gm);
    sh_e[tid] = e;
    float s = e;
#pragma unroll
    for (int o = 16; o; o >>= 1)
        s += __shfl_xor_sync(0xffffffffu, s, o);
    if (lane == 0) red[warp] = s;
    __syncthreads();
    if (warp == 0) {
        float x = red[lane];
#pragma unroll
        for (int o = 16; o; o >>= 1)
            x += __shfl_xor_sync(0xffffffffu, x, o);
        if (lane == 0) {
            red[34] = x;
            unsigned int la = (unsigned int)__cvta_generic_to_shared(&red[35]);
            unsigned int pa;
            asm("mapa.shared::cluster.u32 %0, %1, %2;"
                : "=r"(pa) : "r"(la), "r"(rank ^ 1u));
            asm volatile("st.shared::cluster.f32 [%0], %1;"
                         :: "r"(pa), "f"(x) : "memory");
        }
    }
    asm volatile("barrier.cluster.arrive.aligned;" ::: "memory");
    asm volatile("barrier.cluster.wait.aligned;"   ::: "memory");
    float inv = 1.0f / (red[34] + red[35]);

    // ---- write normalized probabilities (coalesced 4KB per CTA) ----
    out[(size_t)b * 2048 + rank * 1024 + tid] = sh_e[tid] * inv;
}

extern "C" void kernel_launch(void* const* d_in, const int* in_sizes, int n_in,
                              void* d_out, int out_size)
{
    const float* hidden = (const float*)d_in[0];   // [1, 64, 1024]
    const float* enc    = (const float*)d_in[1];   // [2048, 64, 1024]
    float* out          = (float*)d_out;           // [64, 1, 2048]

    // 64 batches x cluster(2) = 128 CTAs of 1024 threads
    attn_cluster_kernel<<<128, THREADS>>>(hidden, enc, out);
}